// round 14
// baseline (speedup 1.0000x reference)
#include <cuda_runtime.h>
#include <cuda_fp16.h>
#include <mma.h>

using namespace nvcuda;

#define NN 100000
#define NE 1000000
#define DD 64
#define NRELTAB 401
#define BB 8

#define BM 128
#define NH_BLOCKS ((NN + BM - 1) / BM)           // 782 hidden GEMM blocks
#define NR_BLOCKS ((NRELTAB + BM - 1) / BM)      // 4 rel_emb GEMM blocks
#define NQ_BLOCKS 2                              // 8 tqr rows, 4 per block
#define FUSED_BLOCKS (NH_BLOCKS + NR_BLOCKS + NQ_BLOCKS)  // 788

// smem (floats): A16 [128][72]h = 4608f, B16 [64][136]h = 4352f,
// epi/staging region 8704f (staging needs 2*64*65 = 8320f <= 8704f)
#define A16_F 4608
#define B16_F 4352
#define EPI_F 8704
#define FUSED_SMEM ((A16_F + B16_F + EPI_F) * 4)

#define EDGE_ITERS 4
#define EDGE_BLOCKS (NE / (16 * EDGE_ITERS))     // 15625

// Scratch (static device globals — no runtime allocation).
// g_h16: per node, 128 halves: for l in 0..15: hsp[4l..4l+3] then hp2[4l..4l+3]
//   (hsp = hidden@Ws^T, hp2 = hidden@Wh^T)
__device__ __align__(256) __half g_h16[NN * 2 * DD];
// g_trrp: per relation, same interleaved layout: tr = rel_emb@Wr^T, rp2 = rel_emb@Wh^T
__device__ __align__(256) __half g_trrp[NRELTAB * 2 * DD];
__device__ __align__(256) __half g_tqr16[BB * DD];   // rel_emb[q_rel]@Wqr^T + bias

// ---------------------------------------------------------------------------
// Single fused pre-kernel (788 blocks):
//  [0, 782): zero d_out slice + hidden[128 rows] @ [Ws^T|Wh^T] -> g_h16
//  [782, 786): rel_emb[128 rows] @ [Wr^T|Wh^T] -> g_trrp (identical epilogue)
//  [786, 788): tqr rows (rel_emb[q_rel] @ Wqr^T + bias) -> g_tqr16
// Every GEMM block builds its own fp16 B tile: coalesced LDG of the two
// weight matrices into padded fp32 smem (epi region, released before the
// epilogue needs it), conflict-free transposed reads into B16 [64][136]
// (272B stride: LDSM conflict-free). A padded to 72-half rows (144B stride).
// Two passes of c[4]; pass-0 buffered in regs; pass-1 writes combined uint4.
// ---------------------------------------------------------------------------
__global__ __launch_bounds__(256)
void fused_pre_kernel(const float* __restrict__ hidden,
                      const float* __restrict__ Ws,
                      const float* __restrict__ Wh,
                      const float* __restrict__ emb,
                      const float* __restrict__ Wr,
                      const float* __restrict__ Wqr,
                      const float* __restrict__ bias,
                      const int* __restrict__ qrel,
                      float* __restrict__ out) {
    extern __shared__ float sm[];
    int t = threadIdx.x;

    if (blockIdx.x >= NH_BLOCKS + NR_BLOCKS) {
        // ---- tqr path: 4 rows per block ----
        float* WqrS = sm;               // [64][65]
        float* rows = sm + DD * 65;     // [4][64]
        for (int i = t; i < DD * DD; i += 256) {
            int r = i >> 6, c = i & 63;
            WqrS[r * 65 + c] = Wqr[i];
        }
        int sub = t >> 6, a = t & 63;
        int r = (int)(blockIdx.x - NH_BLOCKS - NR_BLOCKS) * 4 + sub;  // 0..7
        int src = qrel[r];
        rows[sub * DD + a] = emb[src * DD + a];
        __syncthreads();

        const float* rw = rows + sub * DD;
        float acc = bias[a];
#pragma unroll
        for (int k = 0; k < DD; k++) acc = fmaf(rw[k], WqrS[a * 65 + k], acc);
        g_tqr16[r * DD + a] = __float2half(acc);
        return;
    }

    // ---- GEMM path (hidden or rel_emb) ----
    bool isRel = blockIdx.x >= NH_BLOCKS;
    const float* src = isRel ? emb : hidden;
    const float* W1  = isRel ? Wr : Ws;   // second weight is Wh in both cases
    int M            = isRel ? NRELTAB : NN;
    __half* dstH     = isRel ? g_trrp : g_h16;
    int row0 = (isRel ? (int)(blockIdx.x - NH_BLOCKS) : (int)blockIdx.x) * BM;

    __half* A16 = (__half*)sm;                // [128][72] halves
    __half* B16 = (__half*)(sm + A16_F);      // [64][136] halves
    float*  epi = sm + A16_F + B16_F;         // staging then epilogue

    if (!isRel) {
        // zero d_out (edge kernel REDs into it)
        int i = blockIdx.x * 256 + t;
        int stride = NH_BLOCKS * 256;
        float4* p = (float4*)out;
        const int n4 = NN * DD / 4;
        for (int j = i; j < n4; j += stride)
            p[j] = make_float4(0.f, 0.f, 0.f, 0.f);
    }

    // Stage W1/Wh coalesced into padded fp32 smem (epi region)
    float* W1S = epi;             // [64][65]
    float* W2S = epi + DD * 65;   // [64][65]
    for (int i = t; i < DD * DD; i += 256) {
        int r = i >> 6, c = i & 63;
        W1S[r * 65 + c] = W1[i];
        W2S[r * 65 + c] = Wh[i];
    }
    // A tile: coalesced float4 loads, fp16 convert, padded stride 72
    for (int i = t; i < BM * DD / 4; i += 256) {
        int m = i >> 4, kc = i & 15;
        float4 v = make_float4(0.f, 0.f, 0.f, 0.f);
        if (row0 + m < M)
            v = ((const float4*)(src + (size_t)(row0 + m) * DD))[kc];
        __half2* dst = (__half2*)(A16 + m * 72 + kc * 4);
        dst[0] = __floats2half2_rn(v.x, v.y);
        dst[1] = __floats2half2_rn(v.z, v.w);
    }
    __syncthreads();
    // Transpose: B16[k][a] = stage[a][k]; stride-65 reads are conflict-free
    for (int i = t; i < DD * 2 * DD; i += 256) {
        int k = i >> 7, a = i & 127;
        float w = (a < DD) ? W1S[a * 65 + k] : W2S[(a - DD) * 65 + k];
        B16[k * 136 + a] = __float2half(w);
    }
    __syncthreads();   // staging reads done -> epi reusable; B16/A16 ready

    int w = t >> 5, lane = t & 31;
    float* csm = epi + w * 16 * 68;
    int l16 = lane & 15, rh = lane >> 4;
    int wrow0 = row0 + w * 16;

    uint2 hb0[8];  // pass-0 results buffered per thread

#pragma unroll
    for (int p = 0; p < 2; p++) {
        wmma::fragment<wmma::accumulator, 16, 16, 16, float> c[4];
#pragma unroll
        for (int j = 0; j < 4; j++) wmma::fill_fragment(c[j], 0.f);

#pragma unroll
        for (int kk = 0; kk < 4; kk++) {
            wmma::fragment<wmma::matrix_a, 16, 16, 16, __half, wmma::row_major> a;
            wmma::load_matrix_sync(a, A16 + (w * 16) * 72 + kk * 16, 72);
#pragma unroll
            for (int j = 0; j < 4; j++) {
                wmma::fragment<wmma::matrix_b, 16, 16, 16, __half, wmma::row_major> b;
                wmma::load_matrix_sync(b, B16 + kk * 16 * 136 + p * 64 + j * 16, 136);
                wmma::mma_sync(c[j], a, b, c[j]);
            }
        }

#pragma unroll
        for (int j = 0; j < 4; j++)
            wmma::store_matrix_sync(csm + j * 16, c[j], 68, wmma::mem_row_major);
        __syncwarp();

#pragma unroll
        for (int it = 0; it < 8; it++) {
            int r = it * 2 + rh;
            float4 v = *(const float4*)(csm + r * 68 + 4 * l16);
            uint2 hb;
            ((__half2*)&hb)[0] = __floats2half2_rn(v.x, v.y);
            ((__half2*)&hb)[1] = __floats2half2_rn(v.z, v.w);
            if (p == 0) {
                hb0[it] = hb;
            } else if (wrow0 + r < M) {
                uint4 full;
                full.x = hb0[it].x; full.y = hb0[it].y;
                full.z = hb.x;      full.w = hb.y;
                *(uint4*)(dstH + (size_t)(wrow0 + r) * 128 + l16 * 8) = full;
            }
        }
        __syncwarp();
    }
}

// ---------------------------------------------------------------------------
// Edge kernel (unchanged: ~67us measured). 16 lanes/edge, 4 edges/group,
// hoisted wv/wb, red.global.add.v4.f32 into d_out.
// ---------------------------------------------------------------------------
__global__ __launch_bounds__(256)
void edge_kernel(const int* __restrict__ edges,
                 const float* __restrict__ walpha_w,
                 const float* __restrict__ walpha_b,
                 float* __restrict__ out) {
    unsigned gtid = blockIdx.x * blockDim.x + threadIdx.x;
    unsigned g = gtid >> 4;
    int l = gtid & 15;

    const float4 wv = __ldg((const float4*)walpha_w + l);
    const float wb = __ldg(walpha_b);
    unsigned eid0 = g * EDGE_ITERS;

#pragma unroll
    for (int it = 0; it < EDGE_ITERS; it++) {
        unsigned eid = eid0 + it;
        const int* e = edges + (size_t)eid * 6;
        int v = 0;
        if (l < 4) v = __ldg(e + ((0x5420u >> (l * 4)) & 0xF));  // cols 0,2,4,5
        int r_idx = __shfl_sync(0xffffffffu, v, 0, 16);
        int rel   = __shfl_sync(0xffffffffu, v, 1, 16);
        int sub   = __shfl_sync(0xffffffffu, v, 2, 16);
        int obj   = __shfl_sync(0xffffffffu, v, 3, 16);

        uint4 h  = __ldg((const uint4*)(g_h16 + (size_t)sub * 2 * DD) + l);
        uint4 tt = __ldg((const uint4*)(g_trrp + rel * 2 * DD) + l);
        uint2 tq = __ldg((const uint2*)(g_tqr16 + r_idx * DD) + l);

        float2 a0 = __half22float2(*(const __half2*)&h.x);
        float2 a1 = __half22float2(*(const __half2*)&h.y);
        float2 b0 = __half22float2(*(const __half2*)&h.z);
        float2 b1 = __half22float2(*(const __half2*)&h.w);
        float2 t0 = __half22float2(*(const __half2*)&tt.x);
        float2 t1 = __half22float2(*(const __half2*)&tt.y);
        float2 r0 = __half22float2(*(const __half2*)&tt.z);
        float2 r1 = __half22float2(*(const __half2*)&tt.w);
        float2 q0 = __half22float2(*(const __half2*)&tq.x);
        float2 q1 = __half22float2(*(const __half2*)&tq.y);

        float p0 = fmaxf(a0.x + t0.x + q0.x, 0.f);
        float p1 = fmaxf(a0.y + t0.y + q0.y, 0.f);
        float p2 = fmaxf(a1.x + t1.x + q1.x, 0.f);
        float p3 = fmaxf(a1.y + t1.y + q1.y, 0.f);
        float part = fmaf(p0, wv.x, fmaf(p1, wv.y, fmaf(p2, wv.z, p3 * wv.w)));
#pragma unroll
        for (int o = 8; o > 0; o >>= 1)
            part += __shfl_xor_sync(0xffffffffu, part, o);

        float alpha = 1.f / (1.f + __expf(-(part + wb)));

        float m0 = alpha * (b0.x + r0.x);
        float m1 = alpha * (b0.y + r0.y);
        float m2 = alpha * (b1.x + r1.x);
        float m3 = alpha * (b1.y + r1.y);

        float* dst = out + (size_t)obj * DD + l * 4;
        asm volatile("red.global.add.v4.f32 [%0], {%1, %2, %3, %4};"
                     :: "l"(dst), "f"(m0), "f"(m1), "f"(m2), "f"(m3)
                     : "memory");
    }
}

// ---------------------------------------------------------------------------
// Inputs (metadata order):
//  0 q_sub[8] i32, 1 q_rel[8] i32, 2 hidden[100000,64] f32, 3 edges[1000000,6] i32,
//  4 nodes[100000,2] i32, 5 old_nodes_new_idx[50000] i32, 6 batchsize i32,
//  7 rel_emb[401,64] f32, 8 Ws[64,64], 9 Wr[64,64], 10 Wqr_w[64,64], 11 Wqr_b[64],
// 12 walpha_w[1,64], 13 walpha_b[1], 14 Wh[64,64]
// Output: hidden_new[100000,64] f32
// ---------------------------------------------------------------------------
extern "C" void kernel_launch(void* const* d_in, const int* in_sizes, int n_in,
                              void* d_out, int out_size) {
    const int*   q_rel    = (const int*)d_in[1];
    const float* hidden   = (const float*)d_in[2];
    const int*   edges    = (const int*)d_in[3];
    const float* rel_emb  = (const float*)d_in[7];
    const float* Ws       = (const float*)d_in[8];
    const float* Wr       = (const float*)d_in[9];
    const float* Wqr_w    = (const float*)d_in[10];
    const float* Wqr_b    = (const float*)d_in[11];
    const float* walpha_w = (const float*)d_in[12];
    const float* walpha_b = (const float*)d_in[13];
    const float* Wh       = (const float*)d_in[14];
    float* out = (float*)d_out;

    cudaFuncSetAttribute(fused_pre_kernel,
                         cudaFuncAttributeMaxDynamicSharedMemorySize, FUSED_SMEM);

    fused_pre_kernel<<<FUSED_BLOCKS, 256, FUSED_SMEM>>>(
        hidden, Ws, Wh, rel_emb, Wr, Wqr_w, Wqr_b, q_rel, out);
    edge_kernel<<<EDGE_BLOCKS, 256>>>(edges, walpha_w, walpha_b, out);
}

// round 15
// speedup vs baseline: 1.0767x; 1.0767x over previous
#include <cuda_runtime.h>
#include <cuda_fp16.h>
#include <mma.h>

using namespace nvcuda;

#define NN 100000
#define NE 1000000
#define DD 64
#define NRELTAB 401
#define BB 8

#define BM 128
#define NGEMM_BLOCKS ((NN + BM - 1) / BM)        // 782
#define NPROJ_ROWS (2 * NRELTAB + BB)            // 810
#define NPROJ_BLOCKS ((NPROJ_ROWS + 3) / 4)      // 203
#define PREP_BLOCKS (NPROJ_BLOCKS + 1)           // 204
#define PREP_SMEM (3 * DD * 65 * 4 + 4 * DD * 4)

// GEMM smem (floats): A16 [128][72]h = 4608f, B16 [64][136]h = 4352f,
// epi 8 warps * [16][68]f = 8704f  -> 70656 B (3 CTAs/SM)
#define A16_F 4608
#define B16_F 4352
#define GEMM_SMEM ((A16_F + B16_F + 8704) * 4)

#define EDGE_ITERS 4
#define EDGE_BLOCKS (NE / (16 * EDGE_ITERS))     // 15625

// Scratch (static device globals — no runtime allocation).
__device__ __align__(256) __half g_W16[DD * 2 * DD];  // [k][a]: a<64 Ws^T, else Wh^T
// g_h16: per node, 128 halves: for l in 0..15: hsp[4l..4l+3] then hp2[4l..4l+3]
__device__ __align__(256) __half g_h16[NN * 2 * DD];
// g_trrp: per relation, 128 halves: for l: tr[4l..4l+3], rp2[4l..4l+3]
__device__ __align__(256) __half g_trrp[NRELTAB * 2 * DD];
__device__ __align__(256) __half g_tqr16[BB * DD];    // rel_emb[q_rel]@Wqr^T + bias

// ---------------------------------------------------------------------------
// Prep kernel: relation projections (203 blocks) + one block building g_W16.
// (identical to R13 — 12.6us, overlaps poorly but proven)
// ---------------------------------------------------------------------------
__global__ __launch_bounds__(256)
void prep_kernel(const float* __restrict__ emb,
                 const float* __restrict__ Wr,
                 const float* __restrict__ Wh,
                 const float* __restrict__ Wqr,
                 const float* __restrict__ bias,
                 const int* __restrict__ qrel,
                 const float* __restrict__ Ws) {
    extern __shared__ float sm[];
    int t = threadIdx.x;

    if (blockIdx.x < NPROJ_BLOCKS) {
        float* WrS  = sm;               // [64][65]
        float* WhS  = sm + DD * 65;     // [64][65]
        float* WqrS = sm + 2 * DD * 65; // [64][65]
        float* rows = sm + 3 * DD * 65; // [4][64]
        for (int i = t; i < DD * DD; i += 256) {
            int r = i >> 6, c = i & 63;
            WrS [r * 65 + c] = Wr[i];
            WhS [r * 65 + c] = Wh[i];
            WqrS[r * 65 + c] = Wqr[i];
        }
        int sub = t >> 6, a = t & 63;
        int rid = blockIdx.x * 4 + sub;
        bool valid = rid < NPROJ_ROWS;
        int seg = valid ? ((rid >= 2 * NRELTAB) ? 2 : (rid >= NRELTAB) ? 1 : 0) : 0;
        int r = rid - (seg == 2 ? 2 * NRELTAB : seg == 1 ? NRELTAB : 0);
        int src = valid ? (seg == 2 ? qrel[r] : r) : 0;
        rows[sub * DD + a] = emb[src * DD + a];
        __syncthreads();
        if (!valid) return;

        const float* W = (seg == 2) ? WqrS : (seg == 1) ? WhS : WrS;
        const float* rw = rows + sub * DD;
        float acc = (seg == 2) ? bias[a] : 0.f;
#pragma unroll
        for (int k = 0; k < DD; k++) acc = fmaf(rw[k], W[a * 65 + k], acc);

        __half h = __float2half(acc);
        if (seg == 2) {
            g_tqr16[r * DD + a] = h;
        } else {
            int pos = r * 2 * DD + 8 * (a >> 2) + (a & 3) + (seg == 1 ? 4 : 0);
            g_trrp[pos] = h;
        }
        return;
    }

    // ---- build g_W16 once: coalesced LDG -> padded smem -> transposed STG ----
    float* WsS = sm;            // [64][65]
    float* WhS = sm + DD * 65;  // [64][65]
    for (int i = t; i < DD * DD; i += 256) {
        int r = i >> 6, c = i & 63;
        WsS[r * 65 + c] = Ws[i];
        WhS[r * 65 + c] = Wh[i];
    }
    __syncthreads();
    for (int i = t; i < DD * 2 * DD; i += 256) {
        int k = i >> 7, a = i & 127;
        float w = (a < DD) ? WsS[a * 65 + k] : WhS[(a - DD) * 65 + k];
        g_W16[i] = __float2half(w);  // i == k*128 + a
    }
}

// ---------------------------------------------------------------------------
// GEMM kernel (identical to R13 — ~17us): zero-out prologue; A padded 72h
// rows, B from g_W16 padded 136h rows (both LDSM conflict-free); two passes
// of c[4]; pass-0 reg-buffered; pass-1 writes combined uint4 to g_h16.
// ---------------------------------------------------------------------------
__global__ __launch_bounds__(256)
void gemm_kernel(const float* __restrict__ hidden, float* __restrict__ out) {
    extern __shared__ float sm[];
    __half* A16 = (__half*)sm;                // [128][72] halves
    __half* B16 = (__half*)(sm + A16_F);      // [64][136] halves
    float*  epi = sm + A16_F + B16_F;         // 8 warps * [16][68]

    int t = threadIdx.x;
    int row0 = blockIdx.x * BM;

    {
        int i = blockIdx.x * 256 + t;
        int stride = NGEMM_BLOCKS * 256;
        float4* p = (float4*)out;
        const int n4 = NN * DD / 4;
        for (int j = i; j < n4; j += stride)
            p[j] = make_float4(0.f, 0.f, 0.f, 0.f);
    }

    for (int i = t; i < BM * DD / 4; i += 256) {
        int m = i >> 4, kc = i & 15;
        float4 v = make_float4(0.f, 0.f, 0.f, 0.f);
        if (row0 + m < NN)
            v = ((const float4*)(hidden + (size_t)(row0 + m) * DD))[kc];
        __half2* dst = (__half2*)(A16 + m * 72 + kc * 4);
        dst[0] = __floats2half2_rn(v.x, v.y);
        dst[1] = __floats2half2_rn(v.z, v.w);
    }
    for (int i = t; i < DD * 2 * DD / 8; i += 256) {   // 1024 uint4s, 16/row
        int r = i >> 4, c16 = i & 15;
        *(uint4*)(B16 + r * 136 + c16 * 8) = ((const uint4*)g_W16)[i];
    }
    __syncthreads();

    int w = t >> 5, lane = t & 31;
    float* csm = epi + w * 16 * 68;
    int l16 = lane & 15, rh = lane >> 4;
    int wrow0 = row0 + w * 16;

    uint2 hb0[8];

#pragma unroll
    for (int p = 0; p < 2; p++) {
        wmma::fragment<wmma::accumulator, 16, 16, 16, float> c[4];
#pragma unroll
        for (int j = 0; j < 4; j++) wmma::fill_fragment(c[j], 0.f);

#pragma unroll
        for (int kk = 0; kk < 4; kk++) {
            wmma::fragment<wmma::matrix_a, 16, 16, 16, __half, wmma::row_major> a;
            wmma::load_matrix_sync(a, A16 + (w * 16) * 72 + kk * 16, 72);
#pragma unroll
            for (int j = 0; j < 4; j++) {
                wmma::fragment<wmma::matrix_b, 16, 16, 16, __half, wmma::row_major> b;
                wmma::load_matrix_sync(b, B16 + kk * 16 * 136 + p * 64 + j * 16, 136);
                wmma::mma_sync(c[j], a, b, c[j]);
            }
        }

#pragma unroll
        for (int j = 0; j < 4; j++)
            wmma::store_matrix_sync(csm + j * 16, c[j], 68, wmma::mem_row_major);
        __syncwarp();

#pragma unroll
        for (int it = 0; it < 8; it++) {
            int r = it * 2 + rh;
            float4 v = *(const float4*)(csm + r * 68 + 4 * l16);
            uint2 hb;
            ((__half2*)&hb)[0] = __floats2half2_rn(v.x, v.y);
            ((__half2*)&hb)[1] = __floats2half2_rn(v.z, v.w);
            if (p == 0) {
                hb0[it] = hb;
            } else if (wrow0 + r < NN) {
                uint4 full;
                full.x = hb0[it].x; full.y = hb0[it].y;
                full.z = hb.x;      full.w = hb.y;
                *(uint4*)(g_h16 + (size_t)(wrow0 + r) * 128 + l16 * 8) = full;
            }
        }
        __syncwarp();
    }
}

// ---------------------------------------------------------------------------
// Edge kernel: alpha path now in half2 (4 hadd2 + 2 hmax2 + 2 cvt vs 22
// scalar fp32 slots) — sigmoid attenuates the extra fp16 rounding, so
// output error is unaffected. Message path stays fp32 (its rounding lands
// directly on the output). Everything else unchanged from the 67us version.
// ---------------------------------------------------------------------------
__global__ __launch_bounds__(256)
void edge_kernel(const int* __restrict__ edges,
                 const float* __restrict__ walpha_w,
                 const float* __restrict__ walpha_b,
                 float* __restrict__ out) {
    unsigned gtid = blockIdx.x * blockDim.x + threadIdx.x;
    unsigned g = gtid >> 4;
    int l = gtid & 15;

    const float4 wv = __ldg((const float4*)walpha_w + l);
    const float wb = __ldg(walpha_b);
    const __half2 hzero = __float2half2_rn(0.f);
    unsigned eid0 = g * EDGE_ITERS;

#pragma unroll
    for (int it = 0; it < EDGE_ITERS; it++) {
        unsigned eid = eid0 + it;
        const int* e = edges + (size_t)eid * 6;
        int v = 0;
        if (l < 4) v = __ldg(e + ((0x5420u >> (l * 4)) & 0xF));  // cols 0,2,4,5
        int r_idx = __shfl_sync(0xffffffffu, v, 0, 16);
        int rel   = __shfl_sync(0xffffffffu, v, 1, 16);
        int sub   = __shfl_sync(0xffffffffu, v, 2, 16);
        int obj   = __shfl_sync(0xffffffffu, v, 3, 16);

        uint4 h  = __ldg((const uint4*)(g_h16 + (size_t)sub * 2 * DD) + l);
        uint4 tt = __ldg((const uint4*)(g_trrp + rel * 2 * DD) + l);
        uint2 tq = __ldg((const uint2*)(g_tqr16 + r_idx * DD) + l);

        // alpha path in half2: pre = relu(hsp + tr + tqr)
        __half2 p01 = __hmax2(__hadd2(__hadd2(*(const __half2*)&h.x,
                                              *(const __half2*)&tt.x),
                                      *(const __half2*)&tq.x), hzero);
        __half2 p23 = __hmax2(__hadd2(__hadd2(*(const __half2*)&h.y,
                                              *(const __half2*)&tt.y),
                                      *(const __half2*)&tq.y), hzero);
        float2 f01 = __half22float2(p01);
        float2 f23 = __half22float2(p23);
        float part = fmaf(f01.x, wv.x, fmaf(f01.y, wv.y,
                     fmaf(f23.x, wv.z, f23.y * wv.w)));
#pragma unroll
        for (int o = 8; o > 0; o >>= 1)
            part += __shfl_xor_sync(0xffffffffu, part, o);

        float alpha = 1.f / (1.f + __expf(-(part + wb)));

        // message path in fp32: alpha * (hp2 + rp2)
        float2 b0 = __half22float2(*(const __half2*)&h.z);
        float2 b1 = __half22float2(*(const __half2*)&h.w);
        float2 r0 = __half22float2(*(const __half2*)&tt.z);
        float2 r1 = __half22float2(*(const __half2*)&tt.w);

        float m0 = alpha * (b0.x + r0.x);
        float m1 = alpha * (b0.y + r0.y);
        float m2 = alpha * (b1.x + r1.x);
        float m3 = alpha * (b1.y + r1.y);

        float* dst = out + (size_t)obj * DD + l * 4;
        asm volatile("red.global.add.v4.f32 [%0], {%1, %2, %3, %4};"
                     :: "l"(dst), "f"(m0), "f"(m1), "f"(m2), "f"(m3)
                     : "memory");
    }
}

// ---------------------------------------------------------------------------
// Inputs (metadata order):
//  0 q_sub[8] i32, 1 q_rel[8] i32, 2 hidden[100000,64] f32, 3 edges[1000000,6] i32,
//  4 nodes[100000,2] i32, 5 old_nodes_new_idx[50000] i32, 6 batchsize i32,
//  7 rel_emb[401,64] f32, 8 Ws[64,64], 9 Wr[64,64], 10 Wqr_w[64,64], 11 Wqr_b[64],
// 12 walpha_w[1,64], 13 walpha_b[1], 14 Wh[64,64]
// Output: hidden_new[100000,64] f32
// ---------------------------------------------------------------------------
extern "C" void kernel_launch(void* const* d_in, const int* in_sizes, int n_in,
                              void* d_out, int out_size) {
    const int*   q_rel    = (const int*)d_in[1];
    const float* hidden   = (const float*)d_in[2];
    const int*   edges    = (const int*)d_in[3];
    const float* rel_emb  = (const float*)d_in[7];
    const float* Ws       = (const float*)d_in[8];
    const float* Wr       = (const float*)d_in[9];
    const float* Wqr_w    = (const float*)d_in[10];
    const float* Wqr_b    = (const float*)d_in[11];
    const float* walpha_w = (const float*)d_in[12];
    const float* walpha_b = (const float*)d_in[13];
    const float* Wh       = (const float*)d_in[14];
    float* out = (float*)d_out;

    cudaFuncSetAttribute(prep_kernel,
                         cudaFuncAttributeMaxDynamicSharedMemorySize, PREP_SMEM);
    cudaFuncSetAttribute(gemm_kernel,
                         cudaFuncAttributeMaxDynamicSharedMemorySize, GEMM_SMEM);

    prep_kernel<<<PREP_BLOCKS, 256, PREP_SMEM>>>(rel_emb, Wr, Wh, Wqr_w, Wqr_b,
                                                 q_rel, Ws);
    gemm_kernel<<<NGEMM_BLOCKS, 256, GEMM_SMEM>>>(hidden, out);
    edge_kernel<<<EDGE_BLOCKS, 256>>>(edges, walpha_w, walpha_b, out);
}